// round 8
// baseline (speedup 1.0000x reference)
#include <cuda_runtime.h>
#include <math.h>
#include <stdint.h>

// Problem dims
#define SQ   2048
#define EMB  1280
#define NH   16
#define HD   80
#define FF   5120
#define NL   8
#define OUTD 3584

// ---------------- scratch ----------------
__device__ float g_h[SQ * EMB];        // residual (full fp32)
__device__ float g_x[SQ * EMB];        // LN out (tf32-rounded)
__device__ float g_qkv[SQ * 3 * EMB];
__device__ float g_q[NH * SQ * HD];    // rounded + pre-scaled by 1/sqrt(D)
__device__ float g_k[NH * SQ * HD];
__device__ float g_v[NH * SQ * HD];
__device__ float g_of[SQ * EMB];
__device__ float g_y[SQ * FF];

// tf32-rounded weights, filled once per launch
#define OFF_QKV  0
#define OFF_PROJ 39321600
#define OFF_FC1  52428800
#define OFF_FC2  104857600
#define OFF_M1   157286400
#define OFF_M2   183500800
#define W_TOTAL  201850880
__device__ float g_w[W_TOTAL];

enum { ACT_NONE = 0, ACT_RESID = 1, ACT_QGELU = 2, ACT_GELU = 3 };

// ---------------- tf32 helpers ----------------
__device__ __forceinline__ uint32_t f2tf(float x) {
    uint32_t r;
    asm("cvt.rna.tf32.f32 %0, %1;" : "=r"(r) : "f"(x));
    return r;
}
__device__ __forceinline__ float rndtf(float x) {
    return __uint_as_float(f2tf(x));
}

#define MMA_TF32(d, a, b) \
    asm volatile("mma.sync.aligned.m16n8k8.row.col.f32.tf32.tf32.f32 " \
                 "{%0,%1,%2,%3},{%4,%5,%6,%7},{%8,%9},{%0,%1,%2,%3};" \
                 : "+f"((d)[0]), "+f"((d)[1]), "+f"((d)[2]), "+f"((d)[3]) \
                 : "r"((a)[0]), "r"((a)[1]), "r"((a)[2]), "r"((a)[3]), \
                   "r"((b)[0]), "r"((b)[1]))

#define LDSM4(r0, r1, r2, r3, addr) \
    asm volatile("ldmatrix.sync.aligned.m8n8.x4.shared.b16 {%0,%1,%2,%3}, [%4];" \
                 : "=r"(r0), "=r"(r1), "=r"(r2), "=r"(r3) : "r"(addr))

__device__ __forceinline__ void cp16(uint32_t dst, const float* src) {
    asm volatile("cp.async.cg.shared.global [%0], [%1], 16;" :: "r"(dst), "l"(src));
}
#define CP_COMMIT() asm volatile("cp.async.commit_group;")
#define CP_WAIT1()  asm volatile("cp.async.wait_group 1;" ::: "memory")

// ---------------- small kernels ----------------

__global__ void copy_kernel(const float* __restrict__ src, float* __restrict__ dst, int n) {
    int i = blockIdx.x * blockDim.x + threadIdx.x;
    if (i < n) dst[i] = src[i];
}

__global__ void roundw_kernel(const float* __restrict__ src, float* __restrict__ dst, int n4) {
    int i = blockIdx.x * 256 + threadIdx.x;
    if (i >= n4) return;
    float4 v = reinterpret_cast<const float4*>(src)[i];
    v.x = rndtf(v.x); v.y = rndtf(v.y); v.z = rndtf(v.z); v.w = rndtf(v.w);
    reinterpret_cast<float4*>(dst)[i] = v;
}

__global__ void ln_kernel(const float* __restrict__ x, const float* __restrict__ w,
                          const float* __restrict__ b, float* __restrict__ out) {
    __shared__ float red[256];
    int row = blockIdx.x, t = threadIdx.x;
    const float* xr = x + (size_t)row * EMB;
    float v[5];
    float s = 0.f;
#pragma unroll
    for (int i = 0; i < 5; i++) { v[i] = xr[t + i * 256]; s += v[i]; }
    red[t] = s; __syncthreads();
    for (int o = 128; o > 0; o >>= 1) { if (t < o) red[t] += red[t + o]; __syncthreads(); }
    float mean = red[0] * (1.f / EMB);
    __syncthreads();
    s = 0.f;
#pragma unroll
    for (int i = 0; i < 5; i++) { float d = v[i] - mean; s += d * d; }
    red[t] = s; __syncthreads();
    for (int o = 128; o > 0; o >>= 1) { if (t < o) red[t] += red[t + o]; __syncthreads(); }
    float rs = rsqrtf(red[0] * (1.f / EMB) + 1e-6f);
#pragma unroll
    for (int i = 0; i < 5; i++) {
        int c = t + i * 256;
        out[(size_t)row * EMB + c] = rndtf((v[i] - mean) * rs * w[c] + b[c]);
    }
}

// RoPE + head split; outputs tf32-rounded, q pre-scaled by 1/sqrt(HD).
__global__ void rope_kernel(const float* __restrict__ qkv, const float* __restrict__ cosv,
                            const float* __restrict__ sinv) {
    int s = blockIdx.x, h = blockIdx.y, d = threadIdx.x;
    if (d >= HD) return;
    const float* base = qkv + (size_t)s * 3 * EMB;
    float c = cosv[s * HD + d], sn = sinv[s * HD + d];
    int qi = h * HD + d;
    float q = base[qi], k = base[EMB + qi], v = base[2 * EMB + qi];
    float qr, kr;
    if (d < HD / 2) { qr = -base[qi + HD / 2]; kr = -base[EMB + qi + HD / 2]; }
    else            { qr =  base[qi - HD / 2]; kr =  base[EMB + qi - HD / 2]; }
    size_t o = ((size_t)h * SQ + s) * HD + d;
    g_q[o] = rndtf((q * c + qr * sn) * 0.11180339887498949f);
    g_k[o] = rndtf(k * c + kr * sn);
    g_v[o] = rndtf(v);
}

__device__ __forceinline__ void epi_store(float* __restrict__ C, const float* __restrict__ bias,
                                          const float* __restrict__ aux, int act, int rnd,
                                          int N, int gm, int gn, float c) {
    if (bias) c += bias[gn];
    if (act == ACT_RESID) {
        c += aux[(size_t)gm * N + gn];
    } else if (act == ACT_QGELU) {
        c = c / (1.f + __expf(-1.702f * c));
    } else if (act == ACT_GELU) {
        c = 0.5f * c * (1.f + erff(c * 0.70710678118654752f));
    }
    if (rnd) c = rndtf(c);
    C[(size_t)gm * N + gn] = c;
}

// ---------------- TN GEMM: C[M,N] = A[M,K] @ B[N,K]^T ----------------
// M,N multiples of 128; K multiple of 32. Inputs tf32-pre-rounded fp32.
// 128 thr = 4 warps, warp grid 2m x 2n, warp tile 64x64. BK=32.
// 3-stage cp.async pipeline; fragments via ldmatrix.x4 (32-bit data as b16 rows).
#define STG_W 4608          // words per operand per stage (128*36)
#define STAGE_W 9216        // words per stage
#define GEMM_SMEM (3 * STAGE_W * 4)

__global__ __launch_bounds__(128, 2) void mma_tn(
    const float* __restrict__ A, const float* __restrict__ B,
    const float* __restrict__ bias, float* __restrict__ C,
    int M, int N, int K, int act, int rnd, const float* __restrict__ aux)
{
    extern __shared__ float sm[];
    const float* Ab = A + (size_t)blockIdx.y * 128 * K;
    const float* Bb = B + (size_t)blockIdx.x * 128 * K;
    uint32_t smb;
    { uint64_t t; asm("cvta.to.shared.u64 %0, %1;" : "=l"(t) : "l"(sm)); smb = (uint32_t)t; }
    int tid = threadIdx.x;
    int warp = tid >> 5, lane = tid & 31;
    int gid = lane >> 2, tq = lane & 3;
    int wm = (warp & 1) * 64, wn = (warp >> 1) * 64;
    int nk = K >> 5;

    // copy coords: 8 float4 per operand per ktile (128 threads)
    int cr[8], cc[8];
#pragma unroll
    for (int i = 0; i < 8; i++) { int f = tid + i * 128; cr[i] = f >> 3; cc[i] = (f & 7) * 4; }

#define ISSUE(kt, s) do { \
    int kb = (kt) * 32; \
    uint32_t sb_ = smb + (uint32_t)(s) * (STAGE_W * 4); \
    _Pragma("unroll") \
    for (int i = 0; i < 8; i++) { \
        cp16(sb_ + (cr[i] * 36 + cc[i]) * 4,         Ab + (size_t)cr[i] * K + kb + cc[i]); \
        cp16(sb_ + (STG_W + cr[i] * 36 + cc[i]) * 4, Bb + (size_t)cr[i] * K + kb + cc[i]); \
    } } while (0)

    // ldmatrix lane-address components
    int rlA = (lane & 7) + ((lane >> 3) & 1) * 8;   // row within 16-row A block
    int kA  = ((lane >> 4) & 1) * 4;                // k offset (matrices 2,3)
    int clB = (lane & 7) + ((lane >> 4) & 1) * 8;   // col within 16-col B block
    int kB  = ((lane >> 3) & 1) * 4;
    uint32_t aoff[4], boff[4];
#pragma unroll
    for (int i = 0; i < 4; i++) {
        aoff[i] = (uint32_t)(((wm + i * 16 + rlA) * 36 + kA) * 4);
        boff[i] = (uint32_t)((STG_W + (wn + i * 16 + clB) * 36 + kB) * 4);
    }

    float acc[4][8][4];
#pragma unroll
    for (int i = 0; i < 4; i++)
#pragma unroll
        for (int j = 0; j < 8; j++)
#pragma unroll
            for (int p = 0; p < 4; p++) acc[i][j][p] = 0.f;

    ISSUE(0, 0); CP_COMMIT();
    if (nk > 1) ISSUE(1, 1);
    CP_COMMIT();

    for (int kt = 0; kt < nk; kt++) {
        CP_WAIT1();
        __syncthreads();
        if (kt + 2 < nk) ISSUE(kt + 2, (kt + 2) % 3);
        CP_COMMIT();
        uint32_t sb = smb + (uint32_t)(kt % 3) * (STAGE_W * 4);
#pragma unroll
        for (int ks = 0; ks < 4; ks++) {
            uint32_t af[4][4], bf[8][2];
#pragma unroll
            for (int im = 0; im < 4; im++)
                LDSM4(af[im][0], af[im][1], af[im][2], af[im][3], sb + aoff[im] + ks * 32);
#pragma unroll
            for (int jp = 0; jp < 4; jp++)
                LDSM4(bf[2 * jp][0], bf[2 * jp][1], bf[2 * jp + 1][0], bf[2 * jp + 1][1],
                      sb + boff[jp] + ks * 32);
#pragma unroll
            for (int im = 0; im < 4; im++)
#pragma unroll
                for (int jn = 0; jn < 8; jn++) MMA_TF32(acc[im][jn], af[im], bf[jn]);
        }
    }

    int row_blk = blockIdx.y * 128, col_blk = blockIdx.x * 128;
#pragma unroll
    for (int im = 0; im < 4; im++) {
#pragma unroll
        for (int jn = 0; jn < 8; jn++) {
            int gm0 = row_blk + wm + im * 16 + gid;
            int gn0 = col_blk + wn + jn * 8 + 2 * tq;
            epi_store(C, bias, aux, act, rnd, N, gm0,     gn0,     acc[im][jn][0]);
            epi_store(C, bias, aux, act, rnd, N, gm0,     gn0 + 1, acc[im][jn][1]);
            epi_store(C, bias, aux, act, rnd, N, gm0 + 8, gn0,     acc[im][jn][2]);
            epi_store(C, bias, aux, act, rnd, N, gm0 + 8, gn0 + 1, acc[im][jn][3]);
        }
    }
#undef ISSUE
}

// ---------------- fused flash attention ----------------
// grid (16 row-blocks, 16 heads), 256 thr = 8 warps; each warp owns 16 full rows.
#define FQ 0
#define FK (128 * 88)
#define FV (2 * 128 * 88)
#define FP (3 * 128 * 88)
#define FLASH_SMEM ((3 * 128 * 88 + 128 * 136) * 4)

__global__ __launch_bounds__(256) void flash_kernel(const float* __restrict__ mask) {
    extern __shared__ uint32_t smu[];
    int rb = blockIdx.x, hb = blockIdx.y;
    const float* Qg = g_q + ((size_t)hb * SQ + rb * 128) * HD;
    const float* Kg = g_k + (size_t)hb * SQ * HD;
    const float* Vg = g_v + (size_t)hb * SQ * HD;
    int tid = threadIdx.x;
    int warp = tid >> 5, lane = tid & 31;
    int gid = lane >> 2, tq = lane & 3;
    int wm = warp * 16;

    for (int i = tid; i < 128 * 20; i += 256) {
        int r = i / 20, c4 = (i % 20) * 4;
        float4 qv = *reinterpret_cast<const float4*>(Qg + (size_t)r * HD + c4);
        int p0 = (c4 & ~7) | ((c4 >> 2) & 1);
        smu[FQ + r * 88 + p0 + 0] = __float_as_uint(qv.x);
        smu[FQ + r * 88 + p0 + 2] = __float_as_uint(qv.y);
        smu[FQ + r * 88 + p0 + 4] = __float_as_uint(qv.z);
        smu[FQ + r * 88 + p0 + 6] = __float_as_uint(qv.w);
    }

    float acc_o[10][4];
#pragma unroll
    for (int j = 0; j < 10; j++)
#pragma unroll
        for (int p = 0; p < 4; p++) acc_o[j][p] = 0.f;
    float M[2] = {-1e30f, -1e30f};
    float L[2] = {0.f, 0.f};

    for (int t0 = 0; t0 < SQ; t0 += 128) {
        __syncthreads();
        for (int i = tid; i < 128 * 20; i += 256) {
            int r = i / 20, c4 = (i % 20) * 4;
            float4 kv = *reinterpret_cast<const float4*>(Kg + (size_t)(t0 + r) * HD + c4);
            float4 vv = *reinterpret_cast<const float4*>(Vg + (size_t)(t0 + r) * HD + c4);
            int p0 = (c4 & ~7) | ((c4 >> 2) & 1);
            smu[FK + r * 88 + p0 + 0] = __float_as_uint(kv.x);
            smu[FK + r * 88 + p0 + 2] = __float_as_uint(kv.y);
            smu[FK + r * 88 + p0 + 4] = __float_as_uint(kv.z);
            smu[FK + r * 88 + p0 + 6] = __float_as_uint(kv.w);
            smu[FV + r * 88 + c4 + 0] = __float_as_uint(vv.x);
            smu[FV + r * 88 + c4 + 1] = __float_as_uint(vv.y);
            smu[FV + r * 88 + c4 + 2] = __float_as_uint(vv.z);
            smu[FV + r * 88 + c4 + 3] = __float_as_uint(vv.w);
        }
        __syncthreads();

        float s[16][4];
#pragma unroll
        for (int j = 0; j < 16; j++)
#pragma unroll
            for (int p = 0; p < 4; p++) s[j][p] = 0.f;
#pragma unroll
        for (int ks = 0; ks < 10; ks++) {
            uint32_t af[4];
            {
                int r = wm + gid;
                uint2 lo = *reinterpret_cast<const uint2*>(&smu[FQ + r * 88 + ks * 8 + 2 * tq]);
                uint2 hi = *reinterpret_cast<const uint2*>(&smu[FQ + (r + 8) * 88 + ks * 8 + 2 * tq]);
                af[0] = lo.x; af[1] = hi.x; af[2] = lo.y; af[3] = hi.y;
            }
#pragma unroll
            for (int jn = 0; jn < 16; jn++) {
                int c = jn * 8 + gid;
                uint2 b = *reinterpret_cast<const uint2*>(&smu[FK + c * 88 + ks * 8 + 2 * tq]);
                uint32_t bf[2] = {b.x, b.y};
                MMA_TF32(s[jn], af, bf);
            }
        }

#pragma unroll
        for (int hf = 0; hf < 2; hf++) {
            int rloc = wm + gid + hf * 8;
            const float* mrow = mask + (size_t)(rb * 128 + rloc) * SQ + t0;
            float mx = -1e30f;
#pragma unroll
            for (int jn = 0; jn < 16; jn++) {
#pragma unroll
                for (int j2 = 0; j2 < 2; j2++) {
                    float c = s[jn][hf * 2 + j2];
                    c += (1.f - mrow[jn * 8 + 2 * tq + j2]) * (-3.402823466e38f);
                    s[jn][hf * 2 + j2] = c;
                    mx = fmaxf(mx, c);
                }
            }
            mx = fmaxf(mx, __shfl_xor_sync(0xffffffffu, mx, 1));
            mx = fmaxf(mx, __shfl_xor_sync(0xffffffffu, mx, 2));
            float Mn = fmaxf(M[hf], mx);
            float f = __expf(M[hf] - Mn);
            M[hf] = Mn;
            float sum = 0.f;
#pragma unroll
            for (int jn = 0; jn < 16; jn++) {
#pragma unroll
                for (int j2 = 0; j2 < 2; j2++) {
                    float p = __expf(s[jn][hf * 2 + j2] - Mn);
                    sum += p;
                    int jloc = 2 * tq + j2;
                    int col = jn * 8 + (((jloc & 3) << 1) | (jloc >> 2));
                    smu[FP + rloc * 136 + col] = f2tf(p);
                }
            }
            sum += __shfl_xor_sync(0xffffffffu, sum, 1);
            sum += __shfl_xor_sync(0xffffffffu, sum, 2);
            L[hf] = L[hf] * f + sum;
#pragma unroll
            for (int jn = 0; jn < 10; jn++) {
                acc_o[jn][hf * 2 + 0] *= f;
                acc_o[jn][hf * 2 + 1] *= f;
            }
        }
        __syncwarp();

#pragma unroll
        for (int ks = 0; ks < 16; ks++) {
            uint32_t af[4];
            {
                int r = wm + gid;
                uint2 lo = *reinterpret_cast<const uint2*>(&smu[FP + r * 136 + ks * 8 + 2 * tq]);
                uint2 hi = *reinterpret_cast<const uint2*>(&smu[FP + (r + 8) * 136 + ks * 8 + 2 * tq]);
                af[0] = lo.x; af[1] = hi.x; af[2] = lo.y; af[3] = hi.y;
            }
#pragma unroll
            for (int jn = 0; jn < 10; jn++) {
                int c = jn * 8 + gid;
                uint32_t bf[2];
                bf[0] = smu[FV + (ks * 8 + tq) * 88 + c];
                bf[1] = smu[FV + (ks * 8 + tq + 4) * 88 + c];
                MMA_TF32(acc_o[jn], af, bf);
            }
        }
    }

#pragma unroll
    for (int jn = 0; jn < 10; jn++) {
#pragma unroll
        for (int idx = 0; idx < 4; idx++) {
            int hf = idx >> 1, j2 = idx & 1;
            int row = rb * 128 + wm + gid + hf * 8;
            int col = jn * 8 + 2 * tq + j2;
            g_of[(size_t)row * EMB + hb * HD + col] = rndtf(acc_o[jn][idx] / L[hf]);
        }
    }
}

// ---------------- host orchestration ----------------
extern "C" void kernel_launch(void* const* d_in, const int* in_sizes, int n_in,
                              void* d_out, int out_size) {
    (void)in_sizes; (void)n_in; (void)out_size;
    const float* hs     = (const float*)d_in[0];
    const float* mask   = (const float*)d_in[1];
    const float* cosv   = (const float*)d_in[2];
    const float* sinv   = (const float*)d_in[3];
    const float* qkv_w  = (const float*)d_in[4];
    const float* qkv_b  = (const float*)d_in[5];
    const float* proj_w = (const float*)d_in[6];
    const float* proj_b = (const float*)d_in[7];
    const float* ln1_w  = (const float*)d_in[8];
    const float* ln1_b  = (const float*)d_in[9];
    const float* ln2_w  = (const float*)d_in[10];
    const float* ln2_b  = (const float*)d_in[11];
    const float* fc1_w  = (const float*)d_in[12];
    const float* fc1_b  = (const float*)d_in[13];
    const float* fc2_w  = (const float*)d_in[14];
    const float* fc2_b  = (const float*)d_in[15];
    const float* mln_w  = (const float*)d_in[16];
    const float* mln_b  = (const float*)d_in[17];
    const float* m1_w   = (const float*)d_in[18];
    const float* m1_b   = (const float*)d_in[19];
    const float* m2_w   = (const float*)d_in[20];
    const float* m2_b   = (const float*)d_in[21];
    float* out = (float*)d_out;

    float *ph, *px, *pqkv, *pof, *py, *pw;
    cudaGetSymbolAddress((void**)&ph,   g_h);
    cudaGetSymbolAddress((void**)&px,   g_x);
    cudaGetSymbolAddress((void**)&pqkv, g_qkv);
    cudaGetSymbolAddress((void**)&pof,  g_of);
    cudaGetSymbolAddress((void**)&py,   g_y);
    cudaGetSymbolAddress((void**)&pw,   g_w);

    cudaFuncSetAttribute(flash_kernel, cudaFuncAttributeMaxDynamicSharedMemorySize, FLASH_SMEM);
    cudaFuncSetAttribute(mma_tn,       cudaFuncAttributeMaxDynamicSharedMemorySize, GEMM_SMEM);

    struct { const float* s; int off; int n; } wj[6] = {
        {qkv_w,  OFF_QKV,  NL * 3 * EMB * EMB},
        {proj_w, OFF_PROJ, NL * EMB * EMB},
        {fc1_w,  OFF_FC1,  NL * FF * EMB},
        {fc2_w,  OFF_FC2,  NL * EMB * FF},
        {m1_w,   OFF_M1,   FF * 4 * EMB},
        {m2_w,   OFF_M2,   OUTD * FF},
    };
    for (int i = 0; i < 6; i++) {
        int n4 = wj[i].n / 4;
        roundw_kernel<<<(n4 + 255) / 256, 256>>>(wj[i].s, pw + wj[i].off, n4);
    }

    copy_kernel<<<(SQ * EMB + 255) / 256, 256>>>(hs, ph, SQ * EMB);

    for (int l = 0; l < NL; l++) {
        ln_kernel<<<SQ, 256>>>(ph, ln1_w + l * EMB, ln1_b + l * EMB, px);
        {   // qkv = x @ qkv_w^T + qkv_b
            dim3 grid(3 * EMB / 128, SQ / 128);
            mma_tn<<<grid, 128, GEMM_SMEM>>>(px, pw + OFF_QKV + (size_t)l * 3 * EMB * EMB,
                                             qkv_b + (size_t)l * 3 * EMB, pqkv,
                                             SQ, 3 * EMB, EMB, ACT_NONE, 0, nullptr);
        }
        rope_kernel<<<dim3(SQ, NH), HD>>>(pqkv, cosv, sinv);
        flash_kernel<<<dim3(SQ / 128, NH), 256, FLASH_SMEM>>>(mask);
        {   // h += of @ proj_w^T + proj_b
            dim3 grid(EMB / 128, SQ / 128);
            mma_tn<<<grid, 128, GEMM_SMEM>>>(pof, pw + OFF_PROJ + (size_t)l * EMB * EMB,
                                             proj_b + (size_t)l * EMB, ph,
                                             SQ, EMB, EMB, ACT_RESID, 0, ph);
        }
        ln_kernel<<<SQ, 256>>>(ph, ln2_w + l * EMB, ln2_b + l * EMB, px);
        {   // y = quickgelu(x @ fc1_w^T + fc1_b), rounded
            dim3 grid(FF / 128, SQ / 128);
            mma_tn<<<grid, 128, GEMM_SMEM>>>(px, pw + OFF_FC1 + (size_t)l * FF * EMB,
                                             fc1_b + (size_t)l * FF, py,
                                             SQ, FF, EMB, ACT_QGELU, 1, nullptr);
        }
        {   // h += y @ fc2_w^T + fc2_b
            dim3 grid(EMB / 128, SQ / 128);
            mma_tn<<<grid, 128, GEMM_SMEM>>>(py, pw + OFF_FC2 + (size_t)l * EMB * FF,
                                             fc2_b + (size_t)l * EMB, ph,
                                             SQ, EMB, FF, ACT_RESID, 0, ph);
        }
    }

    // merge head
    ln_kernel<<<SQ, 256>>>(ph, mln_w, mln_b, px);
    {
        dim3 grid(FF / 128, 512 / 128);
        mma_tn<<<grid, 128, GEMM_SMEM>>>(px, pw + OFF_M1, m1_b, py,
                                         512, FF, 4 * EMB, ACT_GELU, 1, nullptr);
    }
    {
        dim3 grid(OUTD / 128, 512 / 128);
        mma_tn<<<grid, 128, GEMM_SMEM>>>(py, pw + OFF_M2, m2_b, out,
                                         512, OUTD, FF, ACT_NONE, 0, nullptr);
    }
}

// round 12
// speedup vs baseline: 1.1523x; 1.1523x over previous
#include <cuda_runtime.h>
#include <math.h>
#include <stdint.h>

// Problem dims
#define SQ   2048
#define EMB  1280
#define NH   16
#define HD   80
#define FF   5120
#define NL   8
#define OUTD 3584

// ---------------- scratch ----------------
__device__ float g_h[SQ * EMB];        // residual (full fp32)
__device__ float g_x[SQ * EMB];        // LN out (tf32-rounded)
__device__ float g_qkv[SQ * 3 * EMB];
__device__ float g_q[NH * SQ * HD];    // rounded + pre-scaled by 1/sqrt(D)
__device__ float g_k[NH * SQ * HD];
__device__ float g_v[NH * SQ * HD];
__device__ float g_of[SQ * EMB];
__device__ float g_y[SQ * FF];

// tf32-rounded weights, filled once per launch
#define OFF_QKV  0
#define OFF_PROJ 39321600
#define OFF_FC1  52428800
#define OFF_FC2  104857600
#define OFF_M1   157286400
#define OFF_M2   183500800
#define W_TOTAL  201850880
__device__ float g_w[W_TOTAL];

enum { ACT_NONE = 0, ACT_RESID = 1, ACT_QGELU = 2, ACT_GELU = 3 };

// ---------------- tf32 helpers ----------------
__device__ __forceinline__ uint32_t f2tf(float x) {
    uint32_t r;
    asm("cvt.rna.tf32.f32 %0, %1;" : "=r"(r) : "f"(x));
    return r;
}
__device__ __forceinline__ float rndtf(float x) {
    return __uint_as_float(f2tf(x));
}

#define MMA_TF32(d, a, b) \
    asm volatile("mma.sync.aligned.m16n8k8.row.col.f32.tf32.tf32.f32 " \
                 "{%0,%1,%2,%3},{%4,%5,%6,%7},{%8,%9},{%0,%1,%2,%3};" \
                 : "+f"((d)[0]), "+f"((d)[1]), "+f"((d)[2]), "+f"((d)[3]) \
                 : "r"((a)[0]), "r"((a)[1]), "r"((a)[2]), "r"((a)[3]), \
                   "r"((b)[0]), "r"((b)[1]))

#define LDSM4(r0, r1, r2, r3, addr) \
    asm volatile("ldmatrix.sync.aligned.m8n8.x4.shared.b16 {%0,%1,%2,%3}, [%4];" \
                 : "=r"(r0), "=r"(r1), "=r"(r2), "=r"(r3) : "r"(addr))

__device__ __forceinline__ void cp16(uint32_t dst, const float* src) {
    asm volatile("cp.async.cg.shared.global [%0], [%1], 16;" :: "r"(dst), "l"(src));
}
#define CP_COMMIT() asm volatile("cp.async.commit_group;")
#define CP_WAIT1()  asm volatile("cp.async.wait_group 1;" ::: "memory")

// ---------------- small kernels ----------------

__global__ void copy_kernel(const float* __restrict__ src, float* __restrict__ dst, int n) {
    int i = blockIdx.x * blockDim.x + threadIdx.x;
    if (i < n) dst[i] = src[i];
}

__global__ void roundw_kernel(const float* __restrict__ src, float* __restrict__ dst, int n4) {
    int i = blockIdx.x * 256 + threadIdx.x;
    if (i >= n4) return;
    float4 v = reinterpret_cast<const float4*>(src)[i];
    v.x = rndtf(v.x); v.y = rndtf(v.y); v.z = rndtf(v.z); v.w = rndtf(v.w);
    reinterpret_cast<float4*>(dst)[i] = v;
}

__global__ void ln_kernel(const float* __restrict__ x, const float* __restrict__ w,
                          const float* __restrict__ b, float* __restrict__ out) {
    __shared__ float red[256];
    int row = blockIdx.x, t = threadIdx.x;
    const float* xr = x + (size_t)row * EMB;
    float v[5];
    float s = 0.f;
#pragma unroll
    for (int i = 0; i < 5; i++) { v[i] = xr[t + i * 256]; s += v[i]; }
    red[t] = s; __syncthreads();
    for (int o = 128; o > 0; o >>= 1) { if (t < o) red[t] += red[t + o]; __syncthreads(); }
    float mean = red[0] * (1.f / EMB);
    __syncthreads();
    s = 0.f;
#pragma unroll
    for (int i = 0; i < 5; i++) { float d = v[i] - mean; s += d * d; }
    red[t] = s; __syncthreads();
    for (int o = 128; o > 0; o >>= 1) { if (t < o) red[t] += red[t + o]; __syncthreads(); }
    float rs = rsqrtf(red[0] * (1.f / EMB) + 1e-6f);
#pragma unroll
    for (int i = 0; i < 5; i++) {
        int c = t + i * 256;
        out[(size_t)row * EMB + c] = rndtf((v[i] - mean) * rs * w[c] + b[c]);
    }
}

// RoPE + head split; outputs tf32-rounded, q pre-scaled by 1/sqrt(HD).
__global__ void rope_kernel(const float* __restrict__ qkv, const float* __restrict__ cosv,
                            const float* __restrict__ sinv) {
    int s = blockIdx.x, h = blockIdx.y, d = threadIdx.x;
    if (d >= HD) return;
    const float* base = qkv + (size_t)s * 3 * EMB;
    float c = cosv[s * HD + d], sn = sinv[s * HD + d];
    int qi = h * HD + d;
    float q = base[qi], k = base[EMB + qi], v = base[2 * EMB + qi];
    float qr, kr;
    if (d < HD / 2) { qr = -base[qi + HD / 2]; kr = -base[EMB + qi + HD / 2]; }
    else            { qr =  base[qi - HD / 2]; kr =  base[EMB + qi - HD / 2]; }
    size_t o = ((size_t)h * SQ + s) * HD + d;
    g_q[o] = rndtf((q * c + qr * sn) * 0.11180339887498949f);
    g_k[o] = rndtf(k * c + kr * sn);
    g_v[o] = rndtf(v);
}

__device__ __forceinline__ void epi_store(float* __restrict__ C, const float* __restrict__ bias,
                                          const float* __restrict__ aux, int act, int rnd,
                                          int N, int gm, int gn, float c) {
    if (bias) c += bias[gn];
    if (act == ACT_RESID) {
        c += aux[(size_t)gm * N + gn];
    } else if (act == ACT_QGELU) {
        c = c / (1.f + __expf(-1.702f * c));
    } else if (act == ACT_GELU) {
        c = 0.5f * c * (1.f + erff(c * 0.70710678118654752f));
    }
    if (rnd) c = rndtf(c);
    C[(size_t)gm * N + gn] = c;
}

// ---------------- TN GEMM: C[M,N] = A[M,K] @ B[N,K]^T ----------------
// M,N multiples of 128; K multiple of 32. Inputs tf32-pre-rounded fp32.
// 256 thr = 8 warps, warp grid 2m x 4n, warp tile 64x32. BK=32 (R6 skeleton).
// 3-stage cp.async pipeline; fragments via ldmatrix.x4 (32-bit data as b16 rows).
#define STG_W 4608          // words per operand per stage (128*36)
#define STAGE_W 9216        // words per stage
#define GEMM_SMEM (3 * STAGE_W * 4)

__global__ __launch_bounds__(256, 2) void mma_tn(
    const float* __restrict__ A, const float* __restrict__ B,
    const float* __restrict__ bias, float* __restrict__ C,
    int M, int N, int K, int act, int rnd, const float* __restrict__ aux)
{
    extern __shared__ float sm[];
    const float* Ab = A + (size_t)blockIdx.y * 128 * K;
    const float* Bb = B + (size_t)blockIdx.x * 128 * K;
    uint32_t smb;
    { uint64_t t; asm("cvta.to.shared.u64 %0, %1;" : "=l"(t) : "l"(sm)); smb = (uint32_t)t; }
    int tid = threadIdx.x;
    int warp = tid >> 5, lane = tid & 31;
    int gid = lane >> 2, tq = lane & 3;
    int wm = (warp & 1) * 64, wn = (warp >> 1) * 32;
    int nk = K >> 5;

    // per-thread copy coords: 4 float4 per operand per tile (256 threads)
    int cr[4], cc[4];
#pragma unroll
    for (int i = 0; i < 4; i++) { int f = tid + i * 256; cr[i] = f >> 3; cc[i] = (f & 7) * 4; }

#define ISSUE(kt, s) do { \
    int kb = (kt) * 32; \
    uint32_t sb_ = smb + (uint32_t)(s) * (STAGE_W * 4); \
    _Pragma("unroll") \
    for (int i = 0; i < 4; i++) { \
        cp16(sb_ + (cr[i] * 36 + cc[i]) * 4,         Ab + (size_t)cr[i] * K + kb + cc[i]); \
        cp16(sb_ + (STG_W + cr[i] * 36 + cc[i]) * 4, Bb + (size_t)cr[i] * K + kb + cc[i]); \
    } } while (0)

    // ldmatrix lane-address components (verified bit-exact in R8)
    int rlA = (lane & 7) + ((lane >> 3) & 1) * 8;   // row within 16-row A block
    int kA  = ((lane >> 4) & 1) * 4;                // k offset (matrices 2,3)
    int clB = (lane & 7) + ((lane >> 4) & 1) * 8;   // col within 16-col B block
    int kB  = ((lane >> 3) & 1) * 4;
    uint32_t aoff[4], boff[2];
#pragma unroll
    for (int i = 0; i < 4; i++)
        aoff[i] = (uint32_t)(((wm + i * 16 + rlA) * 36 + kA) * 4);
#pragma unroll
    for (int i = 0; i < 2; i++)
        boff[i] = (uint32_t)((STG_W + (wn + i * 16 + clB) * 36 + kB) * 4);

    float acc[4][4][4];
#pragma unroll
    for (int i = 0; i < 4; i++)
#pragma unroll
        for (int j = 0; j < 4; j++)
#pragma unroll
            for (int p = 0; p < 4; p++) acc[i][j][p] = 0.f;

    ISSUE(0, 0); CP_COMMIT();
    if (nk > 1) ISSUE(1, 1);
    CP_COMMIT();

    for (int kt = 0; kt < nk; kt++) {
        CP_WAIT1();
        __syncthreads();
        if (kt + 2 < nk) ISSUE(kt + 2, (kt + 2) % 3);
        CP_COMMIT();
        uint32_t sb = smb + (uint32_t)(kt % 3) * (STAGE_W * 4);
#pragma unroll
        for (int ks = 0; ks < 4; ks++) {
            uint32_t af[4][4], bf[4][2];
#pragma unroll
            for (int im = 0; im < 4; im++)
                LDSM4(af[im][0], af[im][1], af[im][2], af[im][3], sb + aoff[im] + ks * 32);
#pragma unroll
            for (int jp = 0; jp < 2; jp++)
                LDSM4(bf[2 * jp][0], bf[2 * jp][1], bf[2 * jp + 1][0], bf[2 * jp + 1][1],
                      sb + boff[jp] + ks * 32);
#pragma unroll
            for (int im = 0; im < 4; im++)
#pragma unroll
                for (int jn = 0; jn < 4; jn++) MMA_TF32(acc[im][jn], af[im], bf[jn]);
        }
    }

    int row_blk = blockIdx.y * 128, col_blk = blockIdx.x * 128;
#pragma unroll
    for (int im = 0; im < 4; im++) {
#pragma unroll
        for (int jn = 0; jn < 4; jn++) {
            int gm0 = row_blk + wm + im * 16 + gid;
            int gn0 = col_blk + wn + jn * 8 + 2 * tq;
            epi_store(C, bias, aux, act, rnd, N, gm0,     gn0,     acc[im][jn][0]);
            epi_store(C, bias, aux, act, rnd, N, gm0,     gn0 + 1, acc[im][jn][1]);
            epi_store(C, bias, aux, act, rnd, N, gm0 + 8, gn0,     acc[im][jn][2]);
            epi_store(C, bias, aux, act, rnd, N, gm0 + 8, gn0 + 1, acc[im][jn][3]);
        }
    }
#undef ISSUE
}

// ---------------- fused flash attention ----------------
// grid (16 row-blocks, 16 heads), 256 thr = 8 warps; each warp owns 16 full rows.
#define FQ 0
#define FK (128 * 88)
#define FV (2 * 128 * 88)
#define FP (3 * 128 * 88)
#define FLASH_SMEM ((3 * 128 * 88 + 128 * 136) * 4)

__global__ __launch_bounds__(256) void flash_kernel(const float* __restrict__ mask) {
    extern __shared__ uint32_t smu[];
    int rb = blockIdx.x, hb = blockIdx.y;
    const float* Qg = g_q + ((size_t)hb * SQ + rb * 128) * HD;
    const float* Kg = g_k + (size_t)hb * SQ * HD;
    const float* Vg = g_v + (size_t)hb * SQ * HD;
    int tid = threadIdx.x;
    int warp = tid >> 5, lane = tid & 31;
    int gid = lane >> 2, tq = lane & 3;
    int wm = warp * 16;

    for (int i = tid; i < 128 * 20; i += 256) {
        int r = i / 20, c4 = (i % 20) * 4;
        float4 qv = *reinterpret_cast<const float4*>(Qg + (size_t)r * HD + c4);
        int p0 = (c4 & ~7) | ((c4 >> 2) & 1);
        smu[FQ + r * 88 + p0 + 0] = __float_as_uint(qv.x);
        smu[FQ + r * 88 + p0 + 2] = __float_as_uint(qv.y);
        smu[FQ + r * 88 + p0 + 4] = __float_as_uint(qv.z);
        smu[FQ + r * 88 + p0 + 6] = __float_as_uint(qv.w);
    }

    float acc_o[10][4];
#pragma unroll
    for (int j = 0; j < 10; j++)
#pragma unroll
        for (int p = 0; p < 4; p++) acc_o[j][p] = 0.f;
    float M[2] = {-1e30f, -1e30f};
    float L[2] = {0.f, 0.f};

    for (int t0 = 0; t0 < SQ; t0 += 128) {
        __syncthreads();
        for (int i = tid; i < 128 * 20; i += 256) {
            int r = i / 20, c4 = (i % 20) * 4;
            float4 kv = *reinterpret_cast<const float4*>(Kg + (size_t)(t0 + r) * HD + c4);
            float4 vv = *reinterpret_cast<const float4*>(Vg + (size_t)(t0 + r) * HD + c4);
            int p0 = (c4 & ~7) | ((c4 >> 2) & 1);
            smu[FK + r * 88 + p0 + 0] = __float_as_uint(kv.x);
            smu[FK + r * 88 + p0 + 2] = __float_as_uint(kv.y);
            smu[FK + r * 88 + p0 + 4] = __float_as_uint(kv.z);
            smu[FK + r * 88 + p0 + 6] = __float_as_uint(kv.w);
            smu[FV + r * 88 + c4 + 0] = __float_as_uint(vv.x);
            smu[FV + r * 88 + c4 + 1] = __float_as_uint(vv.y);
            smu[FV + r * 88 + c4 + 2] = __float_as_uint(vv.z);
            smu[FV + r * 88 + c4 + 3] = __float_as_uint(vv.w);
        }
        __syncthreads();

        float s[16][4];
#pragma unroll
        for (int j = 0; j < 16; j++)
#pragma unroll
            for (int p = 0; p < 4; p++) s[j][p] = 0.f;
#pragma unroll
        for (int ks = 0; ks < 10; ks++) {
            uint32_t af[4];
            {
                int r = wm + gid;
                uint2 lo = *reinterpret_cast<const uint2*>(&smu[FQ + r * 88 + ks * 8 + 2 * tq]);
                uint2 hi = *reinterpret_cast<const uint2*>(&smu[FQ + (r + 8) * 88 + ks * 8 + 2 * tq]);
                af[0] = lo.x; af[1] = hi.x; af[2] = lo.y; af[3] = hi.y;
            }
#pragma unroll
            for (int jn = 0; jn < 16; jn++) {
                int c = jn * 8 + gid;
                uint2 b = *reinterpret_cast<const uint2*>(&smu[FK + c * 88 + ks * 8 + 2 * tq]);
                uint32_t bf[2] = {b.x, b.y};
                MMA_TF32(s[jn], af, bf);
            }
        }

#pragma unroll
        for (int hf = 0; hf < 2; hf++) {
            int rloc = wm + gid + hf * 8;
            const float* mrow = mask + (size_t)(rb * 128 + rloc) * SQ + t0;
            float mx = -1e30f;
#pragma unroll
            for (int jn = 0; jn < 16; jn++) {
#pragma unroll
                for (int j2 = 0; j2 < 2; j2++) {
                    float c = s[jn][hf * 2 + j2];
                    c += (1.f - mrow[jn * 8 + 2 * tq + j2]) * (-3.402823466e38f);
                    s[jn][hf * 2 + j2] = c;
                    mx = fmaxf(mx, c);
                }
            }
            mx = fmaxf(mx, __shfl_xor_sync(0xffffffffu, mx, 1));
            mx = fmaxf(mx, __shfl_xor_sync(0xffffffffu, mx, 2));
            float Mn = fmaxf(M[hf], mx);
            float f = __expf(M[hf] - Mn);
            M[hf] = Mn;
            float sum = 0.f;
#pragma unroll
            for (int jn = 0; jn < 16; jn++) {
#pragma unroll
                for (int j2 = 0; j2 < 2; j2++) {
                    float p = __expf(s[jn][hf * 2 + j2] - Mn);
                    sum += p;
                    int jloc = 2 * tq + j2;
                    int col = jn * 8 + (((jloc & 3) << 1) | (jloc >> 2));
                    smu[FP + rloc * 136 + col] = f2tf(p);
                }
            }
            sum += __shfl_xor_sync(0xffffffffu, sum, 1);
            sum += __shfl_xor_sync(0xffffffffu, sum, 2);
            L[hf] = L[hf] * f + sum;
#pragma unroll
            for (int jn = 0; jn < 10; jn++) {
                acc_o[jn][hf * 2 + 0] *= f;
                acc_o[jn][hf * 2 + 1] *= f;
            }
        }
        __syncwarp();

#pragma unroll
        for (int ks = 0; ks < 16; ks++) {
            uint32_t af[4];
            {
                int r = wm + gid;
                uint2 lo = *reinterpret_cast<const uint2*>(&smu[FP + r * 136 + ks * 8 + 2 * tq]);
                uint2 hi = *reinterpret_cast<const uint2*>(&smu[FP + (r + 8) * 136 + ks * 8 + 2 * tq]);
                af[0] = lo.x; af[1] = hi.x; af[2] = lo.y; af[3] = hi.y;
            }
#pragma unroll
            for (int jn = 0; jn < 10; jn++) {
                int c = jn * 8 + gid;
                uint32_t bf[2];
                bf[0] = smu[FV + (ks * 8 + tq) * 88 + c];
                bf[1] = smu[FV + (ks * 8 + tq + 4) * 88 + c];
                MMA_TF32(acc_o[jn], af, bf);
            }
        }
    }

#pragma unroll
    for (int jn = 0; jn < 10; jn++) {
#pragma unroll
        for (int idx = 0; idx < 4; idx++) {
            int hf = idx >> 1, j2 = idx & 1;
            int row = rb * 128 + wm + gid + hf * 8;
            int col = jn * 8 + 2 * tq + j2;
            g_of[(size_t)row * EMB + hb * HD + col] = rndtf(acc_o[jn][idx] / L[hf]);
        }
    }
}

// ---------------- host orchestration ----------------
extern "C" void kernel_launch(void* const* d_in, const int* in_sizes, int n_in,
                              void* d_out, int out_size) {
    (void)in_sizes; (void)n_in; (void)out_size;
    const float* hs     = (const float*)d_in[0];
    const float* mask   = (const float*)d_in[1];
    const float* cosv   = (const float*)d_in[2];
    const float* sinv   = (const float*)d_in[3];
    const float* qkv_w  = (const float*)d_in[4];
    const float* qkv_b  = (const float*)d_in[5];
    const float* proj_w = (const float*)d_in[6];
    const float* proj_b = (const float*)d_in[7];
    const float* ln1_w  = (const float*)d_in[8];
    const float* ln1_b  = (const float*)d_in[9];
    const float* ln2_w  = (const float*)d_in[10];
    const float* ln2_b  = (const float*)d_in[11];
    const float* fc1_w  = (const float*)d_in[12];
    const float* fc1_b  = (const float*)d_in[13];
    const float* fc2_w  = (const float*)d_in[14];
    const float* fc2_b  = (const float*)d_in[15];
    const float* mln_w  = (const float*)d_in[16];
    const float* mln_b  = (const float*)d_in[17];
    const float* m1_w   = (const float*)d_in[18];
    const float* m1_b   = (const float*)d_in[19];
    const float* m2_w   = (const float*)d_in[20];
    const float* m2_b   = (const float*)d_in[21];
    float* out = (float*)d_out;

    float *ph, *px, *pqkv, *pof, *py, *pw;
    cudaGetSymbolAddress((void**)&ph,   g_h);
    cudaGetSymbolAddress((void**)&px,   g_x);
    cudaGetSymbolAddress((void**)&pqkv, g_qkv);
    cudaGetSymbolAddress((void**)&pof,  g_of);
    cudaGetSymbolAddress((void**)&py,   g_y);
    cudaGetSymbolAddress((void**)&pw,   g_w);

    cudaFuncSetAttribute(flash_kernel, cudaFuncAttributeMaxDynamicSharedMemorySize, FLASH_SMEM);
    cudaFuncSetAttribute(mma_tn,       cudaFuncAttributeMaxDynamicSharedMemorySize, GEMM_SMEM);

    struct { const float* s; int off; int n; } wj[6] = {
        {qkv_w,  OFF_QKV,  NL * 3 * EMB * EMB},
        {proj_w, OFF_PROJ, NL * EMB * EMB},
        {fc1_w,  OFF_FC1,  NL * FF * EMB},
        {fc2_w,  OFF_FC2,  NL * EMB * FF},
        {m1_w,   OFF_M1,   FF * 4 * EMB},
        {m2_w,   OFF_M2,   OUTD * FF},
    };
    for (int i = 0; i < 6; i++) {
        int n4 = wj[i].n / 4;
        roundw_kernel<<<(n4 + 255) / 256, 256>>>(wj[i].s, pw + wj[i].off, n4);
    }

    copy_kernel<<<(SQ * EMB + 255) / 256, 256>>>(hs, ph, SQ * EMB);

    for (int l = 0; l < NL; l++) {
        ln_kernel<<<SQ, 256>>>(ph, ln1_w + l * EMB, ln1_b + l * EMB, px);
        {   // qkv = x @ qkv_w^T + qkv_b
            dim3 grid(3 * EMB / 128, SQ / 128);
            mma_tn<<<grid, 256, GEMM_SMEM>>>(px, pw + OFF_QKV + (size_t)l * 3 * EMB * EMB,
                                             qkv_b + (size_t)l * 3 * EMB, pqkv,
                                             SQ, 3 * EMB, EMB, ACT_NONE, 0, nullptr);
        }
        rope_kernel<<<dim3(SQ, NH), HD>>>(pqkv, cosv, sinv);
        flash_kernel<<<dim3(SQ / 128, NH), 256, FLASH_SMEM>>>(mask);
        {   // h += of @ proj_w^T + proj_b
            dim3 grid(EMB / 128, SQ / 128);
            mma_tn<<<grid, 256, GEMM_SMEM>>>(pof, pw + OFF_PROJ + (size_t)l * EMB * EMB,
                                             proj_b + (size_t)l * EMB, ph,
                                             SQ, EMB, EMB, ACT_RESID, 0, ph);
        }
        ln_kernel<<<SQ, 256>>>(ph, ln2_w + l * EMB, ln2_b + l * EMB, px);
        {   // y = quickgelu(x @ fc1_w^T + fc1_b), rounded
            dim3 grid(FF / 128, SQ / 128);
            mma_tn<<<grid, 256, GEMM_SMEM>>>(px, pw + OFF_FC1 + (size_t)l * FF * EMB,
                                             fc1_b + (size_t)l * FF, py,
                                             SQ, FF, EMB, ACT_QGELU, 1, nullptr);
        }
        {   // h += y @ fc2_w^T + fc2_b
            dim3 grid(EMB / 128, SQ / 128);
            mma_tn<<<grid, 256, GEMM_SMEM>>>(py, pw + OFF_FC2 + (size_t)l * EMB * FF,
                                             fc2_b + (size_t)l * EMB, ph,
                                             SQ, EMB, FF, ACT_RESID, 0, ph);
        }
    }

    // merge head
    ln_kernel<<<SQ, 256>>>(ph, mln_w, mln_b, px);
    {
        dim3 grid(FF / 128, 512 / 128);
        mma_tn<<<grid, 256, GEMM_SMEM>>>(px, pw + OFF_M1, m1_b, py,
                                         512, FF, 4 * EMB, ACT_GELU, 1, nullptr);
    }
    {
        dim3 grid(OUTD / 128, 512 / 128);
        mma_tn<<<grid, 256, GEMM_SMEM>>>(py, pw + OFF_M2, m2_b, out,
                                         512, OUTD, FF, ACT_NONE, 0, nullptr);
    }
}